// round 14
// baseline (speedup 1.0000x reference)
#include <cuda_runtime.h>
#include <cuda_bf16.h>
#include <cstdint>

#define TEAMN   5
#define BSZ     16384
#define NROW    (BSZ * TEAMN)     // 81920 member rows
#define NPAIR   20
#define NPAIR_U 10                // unique unordered pairs (prod is symmetric)
#define MROW_U  (BSZ * NPAIR_U)   // 163840 unique pair rows
#define NPLAYER 131072
#define PD      256

// ---------------- scratch (static device globals; no runtime allocation) ----
__device__ __nv_bfloat16 g_h1hi[(size_t)NROW * 512];
__device__ __nv_bfloat16 g_h1lo[(size_t)NROW * 512];
__device__ __nv_bfloat16 g_hhi [(size_t)NROW * 256];
__device__ __nv_bfloat16 g_hlo [(size_t)NROW * 256];
__device__ float         g_wh  [(size_t)NROW * 256];
__device__ float         g_o2  [(size_t)BSZ * NPAIR];
__device__ __nv_bfloat16 g_w1hi[512 * 256], g_w1lo[512 * 256];
__device__ __nv_bfloat16 g_w2hi[256 * 512], g_w2lo[256 * 512];
__device__ __nv_bfloat16 g_awhi[256 * 256], g_awlo[256 * 256];
__device__ __nv_bfloat16 g_m1hi[512 * 256], g_m1lo[512 * 256];

__constant__ int c_i1[NPAIR] = {0,0,0,0, 1,1,1,1, 2,2,2,2, 3,3,3,3, 4,4,4,4};
__constant__ int c_i2[NPAIR] = {1,2,3,4, 0,2,3,4, 0,1,3,4, 0,1,2,4, 0,1,2,3};
__constant__ int c_u1[NPAIR_U] = {0,0,0,0, 1,1,1, 2,2, 3};
__constant__ int c_u2[NPAIR_U] = {1,2,3,4, 2,3,4, 3,4, 4};
__constant__ int c_sA[NPAIR_U] = {0,1,2,3, 5,6,7, 10,11, 15};
__constant__ int c_sB[NPAIR_U] = {4,8,12,16, 9,13,17, 14,18, 19};

__device__ __forceinline__ float siluf(float x) { return x / (1.0f + __expf(-x)); }

__device__ __forceinline__ unsigned smem_u32(const void* p) {
    return (unsigned)__cvta_generic_to_shared(p);
}
__device__ __forceinline__ void ldsm_x4(uint32_t* r, unsigned addr) {
    asm volatile("ldmatrix.sync.aligned.m8n8.x4.shared.b16 {%0,%1,%2,%3}, [%4];"
                 : "=r"(r[0]), "=r"(r[1]), "=r"(r[2]), "=r"(r[3]) : "r"(addr));
}
// one x4 delivering B fragments for TWO adjacent n-tiles (k16 each)
__device__ __forceinline__ void ldsm_x4_b2(uint32_t* b0, uint32_t* b1, unsigned addr) {
    asm volatile("ldmatrix.sync.aligned.m8n8.x4.shared.b16 {%0,%1,%2,%3}, [%4];"
                 : "=r"(b0[0]), "=r"(b0[1]), "=r"(b1[0]), "=r"(b1[1]) : "r"(addr));
}
__device__ __forceinline__ void mma16816(float* c, const uint32_t* a, const uint32_t* b) {
    asm volatile(
        "mma.sync.aligned.m16n8k16.row.col.f32.bf16.bf16.f32 "
        "{%0,%1,%2,%3}, {%4,%5,%6,%7}, {%8,%9}, {%0,%1,%2,%3};"
        : "+f"(c[0]), "+f"(c[1]), "+f"(c[2]), "+f"(c[3])
        : "r"(a[0]), "r"(a[1]), "r"(a[2]), "r"(a[3]), "r"(b[0]), "r"(b[1]));
}
__device__ __forceinline__ void cp16(unsigned saddr, const void* g) {
    asm volatile("cp.async.cg.shared.global [%0], [%1], 16;" :: "r"(saddr), "l"(g));
}
#define CP_COMMIT() asm volatile("cp.async.commit_group;" ::: "memory")
#define CP_WAIT1()  asm volatile("cp.async.wait_group 1;" ::: "memory")
#define CP_WAIT0()  asm volatile("cp.async.wait_group 0;" ::: "memory")

__device__ __forceinline__ void store_split2(__nv_bfloat16* hi, __nv_bfloat16* lo,
                                             size_t off, float y0, float y1) {
    __nv_bfloat16 h0 = __float2bfloat16(y0), h1 = __float2bfloat16(y1);
    *(__nv_bfloat162*)(hi + off) = __halves2bfloat162(h0, h1);
    *(__nv_bfloat162*)(lo + off) = __halves2bfloat162(
        __float2bfloat16(y0 - __bfloat162float(h0)),
        __float2bfloat16(y1 - __bfloat162float(h1)));
}

// ---------------------------------------------------------------------------
// Combined weight split: fm_w1, fm_w2, att_w, mlp_w1 -> (hi, lo) bf16 pairs
// ---------------------------------------------------------------------------
#define W1_N 131072
#define W2_N 131072
#define AW_N 65536
#define M1_N 131072
#define WTOT (W1_N + W2_N + AW_N + M1_N)

__global__ void splitw_k(const float* __restrict__ w1, const float* __restrict__ w2,
                         const float* __restrict__ aw, const float* __restrict__ m1,
                         __nv_bfloat16* __restrict__ w1h, __nv_bfloat16* __restrict__ w1l,
                         __nv_bfloat16* __restrict__ w2h, __nv_bfloat16* __restrict__ w2l,
                         __nv_bfloat16* __restrict__ awh, __nv_bfloat16* __restrict__ awl,
                         __nv_bfloat16* __restrict__ m1h, __nv_bfloat16* __restrict__ m1l)
{
    int i = blockIdx.x * 256 + threadIdx.x;
    if (i >= WTOT) return;
    const float* s; __nv_bfloat16 *hi, *lo; int j = i;
    if (j < W1_N)                { s = w1; hi = w1h; lo = w1l; }
    else if ((j -= W1_N) < W2_N) { s = w2; hi = w2h; lo = w2l; }
    else if ((j -= W2_N) < AW_N) { s = aw; hi = awh; lo = awl; }
    else { j -= AW_N;              s = m1; hi = m1h; lo = m1l; }
    float v = s[j];
    __nv_bfloat16 h = __float2bfloat16(v);
    hi[j] = h;
    lo[j] = __float2bfloat16(v - __bfloat162float(h));
}

// ---------------------------------------------------------------------------
// MERGED split-bf16 GEMM, 3-stage cp.async pipeline, ONE sync per K-chunk.
// (R11 kernel, proven — unchanged.)
// ---------------------------------------------------------------------------
#define GEMM_SMEM  98304          // 3 x 32768
#define STAGE_B    32768
#define TILE_B     8192           // 128 x 64 bytes

template <int K, int EP, bool GATHER>
__global__ __launch_bounds__(256, 2)
void mma_gemm_k(const float* __restrict__ Af,
                const __nv_bfloat16* __restrict__ Ahi, const __nv_bfloat16* __restrict__ Alo,
                const __nv_bfloat16* __restrict__ Whi, const __nv_bfloat16* __restrict__ Wlo,
                const float* __restrict__ bias,
                __nv_bfloat16* __restrict__ Chi, __nv_bfloat16* __restrict__ Clo,
                float* __restrict__ Cf, const int* __restrict__ ids, int N)
{
    constexpr int NC = K / 32;
    extern __shared__ __align__(16) __nv_bfloat16 smdyn[];
    __shared__ int idS[128];

    const int t = threadIdx.x;
    const int lane = t & 31, warp = t >> 5;
    const int wm = warp >> 2, wn = warp & 3;
    const int m0 = blockIdx.y * 128, n0 = blockIdx.x * 128;

    if constexpr (GATHER) {
        if (t < 128) idS[t] = ids[m0 + t];
        __syncthreads();
    }

    const int r0 = t >> 2, cc = t & 3;
    const int r1 = r0 + 64;
    const unsigned d0 = (unsigned)(r0 * 64 + ((cc ^ ((r0 >> 1) & 3)) << 4));
    const unsigned d1 = (unsigned)(r1 * 64 + ((cc ^ ((r1 >> 1) & 3)) << 4));
    const int srcoff = cc * 8;
    const unsigned smB = smem_u32(smdyn);

    float acc[4][4][4];
#pragma unroll
    for (int a = 0; a < 4; a++)
#pragma unroll
        for (int b = 0; b < 4; b++)
#pragma unroll
            for (int c = 0; c < 4; c++) acc[a][b][c] = 0.f;

    const int a_mrow = ((lane >> 3) & 1) * 8 + (lane & 7);
    const int a_c16  = lane >> 4;
    const int b_nrow = ((lane >> 4) & 1) * 8 + (lane & 7);
    const int b_c16  = (lane >> 3) & 1;

    auto issue = [&](int c) {
        const int koff = c * 32 + srcoff;
        const unsigned sb = smB + (unsigned)((c % 3) * STAGE_B);
        if constexpr (!GATHER) {
            cp16(sb + d0,              Ahi + (size_t)(m0 + r0) * K + koff);
            cp16(sb + d1,              Ahi + (size_t)(m0 + r1) * K + koff);
            cp16(sb + TILE_B + d0,     Alo + (size_t)(m0 + r0) * K + koff);
            cp16(sb + TILE_B + d1,     Alo + (size_t)(m0 + r1) * K + koff);
        }
        cp16(sb + 2 * TILE_B + d0,     Whi + (size_t)(n0 + r0) * K + koff);
        cp16(sb + 2 * TILE_B + d1,     Whi + (size_t)(n0 + r1) * K + koff);
        cp16(sb + 3 * TILE_B + d0,     Wlo + (size_t)(n0 + r0) * K + koff);
        cp16(sb + 3 * TILE_B + d1,     Wlo + (size_t)(n0 + r1) * K + koff);
        CP_COMMIT();
    };

    float4 rf[4];
    auto ldgA = [&](int c) {
        const int koff = c * 32 + srcoff;
        const float* s0 = Af + (size_t)idS[r0] * K + koff;
        rf[0] = *(const float4*)s0; rf[1] = *(const float4*)(s0 + 4);
        const float* s1 = Af + (size_t)idS[r1] * K + koff;
        rf[2] = *(const float4*)s1; rf[3] = *(const float4*)(s1 + 4);
    };
    auto stsA = [&](int c) {
        char* base = (char*)smdyn + (c % 3) * STAGE_B;
#pragma unroll
        for (int u = 0; u < 2; u++) {
            const float* f = (const float*)&rf[2 * u];
            const unsigned dd = (u == 0) ? d0 : d1;
            __nv_bfloat16 vh[8], vl[8];
#pragma unroll
            for (int j = 0; j < 8; j++) {
                __nv_bfloat16 h = __float2bfloat16(f[j]);
                vh[j] = h;
                vl[j] = __float2bfloat16(f[j] - __bfloat162float(h));
            }
            *(uint4*)(base + dd)          = *(uint4*)vh;
            *(uint4*)(base + TILE_B + dd) = *(uint4*)vl;
        }
    };

    issue(0);
    issue(1);
    if constexpr (GATHER) ldgA(0);

    for (int c = 0; c < NC; c++) {
        if (c + 1 < NC) { CP_WAIT1(); } else { CP_WAIT0(); }
        if constexpr (GATHER) stsA(c);
        __syncthreads();
        if (c + 2 < NC) issue(c + 2);
        if constexpr (GATHER) { if (c + 1 < NC) ldgA(c + 1); }

        const unsigned sb  = smB + (unsigned)((c % 3) * STAGE_B);
        const unsigned aHi = sb;
        const unsigned aLo = sb + TILE_B;
        const unsigned wHi = sb + 2 * TILE_B;
        const unsigned wLo = sb + 3 * TILE_B;
#pragma unroll
        for (int ks = 0; ks < 2; ks++) {
            uint32_t bh[4][2], bl[4][2];
#pragma unroll
            for (int ntp = 0; ntp < 2; ntp++) {
                const int br = wn * 32 + ntp * 16 + b_nrow;
                const int bc = ks * 2 + b_c16;
                const unsigned wo = (unsigned)(br * 64 + ((bc ^ ((br >> 1) & 3)) << 4));
                ldsm_x4_b2(bh[2 * ntp], bh[2 * ntp + 1], wHi + wo);
                ldsm_x4_b2(bl[2 * ntp], bl[2 * ntp + 1], wLo + wo);
            }
#pragma unroll
            for (int mt = 0; mt < 4; mt++) {
                const int ar = wm * 64 + mt * 16 + a_mrow;
                const int ac = ks * 2 + a_c16;
                const unsigned ao = (unsigned)(ar * 64 + ((ac ^ ((ar >> 1) & 3)) << 4));
                uint32_t afh[4], afl[4];
                ldsm_x4(afh, aHi + ao);
                ldsm_x4(afl, aLo + ao);
#pragma unroll
                for (int nt = 0; nt < 4; nt++) mma16816(acc[mt][nt], afh, bh[nt]);
#pragma unroll
                for (int nt = 0; nt < 4; nt++) mma16816(acc[mt][nt], afl, bh[nt]);
#pragma unroll
                for (int nt = 0; nt < 4; nt++) mma16816(acc[mt][nt], afh, bl[nt]);
            }
        }
    }

#pragma unroll
    for (int mt = 0; mt < 4; mt++)
#pragma unroll
        for (int nt = 0; nt < 4; nt++) {
            int row = m0 + wm * 64 + mt * 16 + (lane >> 2);
            int col = n0 + wn * 32 + nt * 8 + ((lane & 3) << 1);
            float2 bz = *(const float2*)(bias + col);
            float* c = acc[mt][nt];
            float y0 = c[0] + bz.x, y1 = c[1] + bz.y;
            float y2 = c[2] + bz.x, y3 = c[3] + bz.y;
            if (EP == 0) { y0 = siluf(y0); y1 = siluf(y1); y2 = siluf(y2); y3 = siluf(y3); }
            if (EP <= 1) {
                store_split2(Chi, Clo, (size_t)row * N + col, y0, y1);
                store_split2(Chi, Clo, (size_t)(row + 8) * N + col, y2, y3);
            } else {
                *(float2*)(Cf + (size_t)row * N + col)       = make_float2(y0, y1);
                *(float2*)(Cf + (size_t)(row + 8) * N + col) = make_float2(y2, y3);
            }
        }
}

// ---------------------------------------------------------------------------
// Pair-MLP over UNIQUE pairs: A-resident product tiles (R11 layout, proven)
// + W stream upgraded to 3-stage cp.async, ONE sync per chunk.
// MMA accumulation order preserved exactly (bit-identical results to R11).
// smem: A 135168 + W 3x20480 + offs 1024 + redS 2048 = 199680 B.
// ---------------------------------------------------------------------------
#define PR_APLO   67584
#define PR_W      135168
#define PR_WST    20480          // per stage: hi 10240 + lo 10240
#define PR_OFF1   196608
#define PR_OFF2   197120
#define PR_RED    197632
#define PAIRS_SMEM 199680

__global__ __launch_bounds__(256)
void pairs_mma_k(const __nv_bfloat16* __restrict__ Hhi, const __nv_bfloat16* __restrict__ Hlo,
                 const __nv_bfloat16* __restrict__ W1hi, const __nv_bfloat16* __restrict__ W1lo,
                 const float* __restrict__ b1, const float* __restrict__ w2,
                 float* __restrict__ O2)
{
    extern __shared__ __align__(16) char sm[];
    __nv_bfloat16* Aphi = (__nv_bfloat16*)sm;               // [128][264]
    __nv_bfloat16* Aplo = (__nv_bfloat16*)(sm + PR_APLO);   // [128][264]
    int*   off1s = (int*)(sm + PR_OFF1);
    int*   off2s = (int*)(sm + PR_OFF2);
    float* redS  = (float*)(sm + PR_RED);                   // [4][128]

    const int t = threadIdx.x, lane = t & 31, warp = t >> 5;
    const int wm = warp >> 2, wn = warp & 3;
    const int m0 = blockIdx.x * 128;
    const unsigned smB = smem_u32(sm);

    if (t < 128) {
        int r = m0 + t, b = r / NPAIR_U, p = r - b * NPAIR_U;
        off1s[t] = (b * TEAMN + c_u1[p]) * 256;
        off2s[t] = (b * TEAMN + c_u2[p]) * 256;
    }
    __syncthreads();

    // W stream: 32 chunks (nn 0..3, kk 0..7), 3-stage cp.async
    auto issueW = [&](int gg) {
        const int nn = gg >> 3, kk = gg & 7;
        const unsigned sb = smB + (unsigned)(PR_W + (gg % 3) * PR_WST);
#pragma unroll
        for (int u = 0; u < 2; u++) {
            int idx = t + u * 256;
            int row = idx >> 2, c16 = idx & 3;
            unsigned dst = (unsigned)(row * 80 + c16 * 16);
            size_t src = (size_t)(nn * 128 + row) * 256 + kk * 32 + c16 * 8;
            cp16(sb + dst,         W1hi + src);
            cp16(sb + 10240 + dst, W1lo + src);
        }
        CP_COMMIT();
    };

    // prologue W loads overlap the product-build phase below
    issueW(0);
    issueW(1);

    // ---- build product tiles (hi/lo) — R11 layout, unchanged ----
    {
        int cidx = t;
#pragma unroll 4
        for (int i = 0; i < 16; i++, cidx += 256) {
            int row = cidx >> 5;
            int ch  = (cidx & 31) << 3;
            int o1 = off1s[row] + ch, o2 = off2s[row] + ch;
            uint4 u1h = *(const uint4*)(Hhi + o1);
            uint4 u1l = *(const uint4*)(Hlo + o1);
            uint4 u2h = *(const uint4*)(Hhi + o2);
            uint4 u2l = *(const uint4*)(Hlo + o2);
            const __nv_bfloat162* p1h = (const __nv_bfloat162*)&u1h;
            const __nv_bfloat162* p1l = (const __nv_bfloat162*)&u1l;
            const __nv_bfloat162* p2h = (const __nv_bfloat162*)&u2h;
            const __nv_bfloat162* p2l = (const __nv_bfloat162*)&u2l;
            __nv_bfloat162 oph[4], opl[4];
#pragma unroll
            for (int j = 0; j < 4; j++) {
                float2 a   = __bfloat1622float2(p1h[j]);
                float2 al  = __bfloat1622float2(p1l[j]);
                float2 b_  = __bfloat1622float2(p2h[j]);
                float2 bl_ = __bfloat1622float2(p2l[j]);
                float f0 = (a.x + al.x) * (b_.x + bl_.x);
                float f1 = (a.y + al.y) * (b_.y + bl_.y);
                __nv_bfloat16 h0 = __float2bfloat16(f0), h1 = __float2bfloat16(f1);
                oph[j] = __halves2bfloat162(h0, h1);
                opl[j] = __halves2bfloat162(
                    __float2bfloat16(f0 - __bfloat162float(h0)),
                    __float2bfloat16(f1 - __bfloat162float(h1)));
            }
            *(uint4*)(Aphi + row * 264 + ch) = *(uint4*)oph;
            *(uint4*)(Aplo + row * 264 + ch) = *(uint4*)opl;
        }
    }

    float rowsum[4][2];
#pragma unroll
    for (int a = 0; a < 4; a++) { rowsum[a][0] = 0.f; rowsum[a][1] = 0.f; }

    const int a_mrow = ((lane >> 3) & 1) * 8 + (lane & 7);
    const int a_kc   = (lane >> 4) * 8;
    const int b_nrow = ((lane >> 4) & 1) * 8 + (lane & 7);
    const int b_kc   = ((lane >> 3) & 1) * 8;
    const unsigned aPhiB = smem_u32(Aphi);
    const unsigned aPloB = smem_u32(Aplo);

    for (int n0i = 0; n0i < 4; n0i++) {
        int n0 = n0i * 128;
        float acc[4][4][4];
#pragma unroll
        for (int a = 0; a < 4; a++)
#pragma unroll
            for (int b = 0; b < 4; b++)
#pragma unroll
                for (int c = 0; c < 4; c++) acc[a][b][c] = 0.f;

        for (int k0 = 0; k0 < 8; k0++) {
            const int gg = n0i * 8 + k0;
            if (gg + 1 < 32) { CP_WAIT1(); } else { CP_WAIT0(); }
            __syncthreads();
            if (gg + 2 < 32) issueW(gg + 2);

            const unsigned wHiB = smB + (unsigned)(PR_W + (gg % 3) * PR_WST);
            const unsigned wLoB = wHiB + 10240;
#pragma unroll
            for (int ks = 0; ks < 2; ks++) {
                int kpos = k0 * 32 + ks * 16;
                uint32_t bh[4][2], blo_[4][2];
#pragma unroll
                for (int ntp = 0; ntp < 2; ntp++) {
                    unsigned wo = 2u * ((wn * 32 + ntp * 16 + b_nrow) * 40 + ks * 16 + b_kc);
                    ldsm_x4_b2(bh[2 * ntp],   bh[2 * ntp + 1],   wHiB + wo);
                    ldsm_x4_b2(blo_[2 * ntp], blo_[2 * ntp + 1], wLoB + wo);
                }
#pragma unroll
                for (int mt = 0; mt < 4; mt++) {
                    unsigned ao = (wm * 64 + mt * 16 + a_mrow) * 264 + kpos + a_kc;
                    uint32_t af[4];
                    ldsm_x4(af, aPhiB + 2u * ao);
#pragma unroll
                    for (int nt = 0; nt < 4; nt++) mma16816(acc[mt][nt], af, bh[nt]);
#pragma unroll
                    for (int nt = 0; nt < 4; nt++) mma16816(acc[mt][nt], af, blo_[nt]);
                    ldsm_x4(af, aPloB + 2u * ao);
#pragma unroll
                    for (int nt = 0; nt < 4; nt++) mma16816(acc[mt][nt], af, bh[nt]);
                }
            }
        }
        // fold this n-chunk into rowsums
#pragma unroll
        for (int mt = 0; mt < 4; mt++)
#pragma unroll
            for (int nt = 0; nt < 4; nt++) {
                int col = n0 + wn * 32 + nt * 8 + ((lane & 3) << 1);
                float2 bz = *(const float2*)(b1 + col);
                float2 wz = *(const float2*)(w2 + col);
                float* c = acc[mt][nt];
                rowsum[mt][0] += siluf(c[0] + bz.x) * wz.x + siluf(c[1] + bz.y) * wz.y;
                rowsum[mt][1] += siluf(c[2] + bz.x) * wz.x + siluf(c[3] + bz.y) * wz.y;
            }
    }

    // reduce over the 4 lanes sharing a row, then across the 4 n-warps
#pragma unroll
    for (int mt = 0; mt < 4; mt++)
#pragma unroll
        for (int p = 0; p < 2; p++) {
            float v = rowsum[mt][p];
            v += __shfl_xor_sync(0xffffffffu, v, 1);
            v += __shfl_xor_sync(0xffffffffu, v, 2);
            rowsum[mt][p] = v;
        }
    __syncthreads();
    if ((lane & 3) == 0) {
#pragma unroll
        for (int mt = 0; mt < 4; mt++)
#pragma unroll
            for (int p = 0; p < 2; p++) {
                int r = wm * 64 + mt * 16 + (lane >> 2) + p * 8;
                redS[wn * 128 + r] = rowsum[mt][p];
            }
    }
    __syncthreads();
    if (t < 128) {
        float v = redS[t] + redS[128 + t] + redS[256 + t] + redS[384 + t];
        int r = m0 + t, b = r / NPAIR_U, p = r - b * NPAIR_U;
        O2[b * NPAIR + c_sA[p]] = v;   // (i,j)
        O2[b * NPAIR + c_sB[p]] = v;   // (j,i) — identical by symmetry
    }
}

// ---------------------------------------------------------------------------
// Final: score[p] = <wh[b,i1], h[b,i2]>, softmax per group-of-4, weighted sum.
// ---------------------------------------------------------------------------
__global__ __launch_bounds__(128)
void final_k(const __nv_bfloat16* __restrict__ Hhi, const __nv_bfloat16* __restrict__ Hlo,
             const float* __restrict__ WH, const float* __restrict__ O2,
             const float* __restrict__ mlp_b2, float* __restrict__ out)
{
    __shared__ float scoreS[4][NPAIR];
    const int wi = threadIdx.x >> 5, lane = threadIdx.x & 31;
    const int b = blockIdx.x * 4 + wi;
    const __nv_bfloat16* hbh = Hhi + (size_t)b * TEAMN * 256;
    const __nv_bfloat16* hbl = Hlo + (size_t)b * TEAMN * 256;
    const float* whb = WH + (size_t)b * TEAMN * 256;

    for (int p = 0; p < NPAIR; p++) {
        const float* wa = whb + c_i1[p] * 256;
        int ho = c_i2[p] * 256 + lane * 8;
        uint4 uh = *(const uint4*)(hbh + ho);
        uint4 ul = *(const uint4*)(hbl + ho);
        const __nv_bfloat162* ph = (const __nv_bfloat162*)&uh;
        const __nv_bfloat162* pl = (const __nv_bfloat162*)&ul;
        float xv[8];
        *(float4*)&xv[0] = *(const float4*)(wa + lane * 8);
        *(float4*)&xv[4] = *(const float4*)(wa + lane * 8 + 4);
        float s = 0.f;
#pragma unroll
        for (int j = 0; j < 4; j++) {
            float2 hh = __bfloat1622float2(ph[j]);
            float2 hl = __bfloat1622float2(pl[j]);
            s += xv[2 * j] * (hh.x + hl.x) + xv[2 * j + 1] * (hh.y + hl.y);
        }
#pragma unroll
        for (int off = 16; off > 0; off >>= 1)
            s += __shfl_down_sync(0xffffffffu, s, off);
        if (lane == 0) scoreS[wi][p] = s;
    }
    __syncwarp();

    float partial = 0.f;
    if (lane < TEAMN) {
        float sc[4];
#pragma unroll
        for (int j = 0; j < 4; j++) sc[j] = scoreS[wi][lane * 4 + j];
        float mx = fmaxf(fmaxf(sc[0], sc[1]), fmaxf(sc[2], sc[3]));
        float e[4], se = 0.f;
#pragma unroll
        for (int j = 0; j < 4; j++) { e[j] = __expf(sc[j] - mx); se += e[j]; }
        float bias2 = mlp_b2[0];
        float acc = 0.f;
#pragma unroll
        for (int j = 0; j < 4; j++)
            acc += e[j] * (O2[b * NPAIR + lane * 4 + j] + bias2);
        partial = acc / se;
    }
#pragma unroll
    for (int off = 16; off > 0; off >>= 1)
        partial += __shfl_down_sync(0xffffffffu, partial, off);
    if (lane == 0) out[b] = partial;
}

// ---------------------------------------------------------------------------
extern "C" void kernel_launch(void* const* d_in, const int* in_sizes, int n_in,
                              void* d_out, int out_size)
{
    const int*   team_ids = (const int*)  d_in[0];
    const float* emb      = (const float*)d_in[1];
    const float* fm_w1    = (const float*)d_in[2];
    const float* fm_b1    = (const float*)d_in[3];
    const float* fm_w2    = (const float*)d_in[4];
    const float* fm_b2    = (const float*)d_in[5];
    const float* att_w    = (const float*)d_in[6];
    const float* att_b    = (const float*)d_in[7];
    const float* mlp_w1   = (const float*)d_in[8];
    const float* mlp_b1   = (const float*)d_in[9];
    const float* mlp_w2   = (const float*)d_in[10];
    const float* mlp_b2   = (const float*)d_in[11];
    float* out = (float*)d_out;

    void *p_h1hi, *p_h1lo, *p_hhi, *p_hlo, *p_wh, *p_o2;
    void *p_w1hi, *p_w1lo, *p_w2hi, *p_w2lo, *p_awhi, *p_awlo, *p_m1hi, *p_m1lo;
    cudaGetSymbolAddress(&p_h1hi, g_h1hi); cudaGetSymbolAddress(&p_h1lo, g_h1lo);
    cudaGetSymbolAddress(&p_hhi,  g_hhi);  cudaGetSymbolAddress(&p_hlo,  g_hlo);
    cudaGetSymbolAddress(&p_wh,   g_wh);   cudaGetSymbolAddress(&p_o2,   g_o2);
    cudaGetSymbolAddress(&p_w1hi, g_w1hi); cudaGetSymbolAddress(&p_w1lo, g_w1lo);
    cudaGetSymbolAddress(&p_w2hi, g_w2hi); cudaGetSymbolAddress(&p_w2lo, g_w2lo);
    cudaGetSymbolAddress(&p_awhi, g_awhi); cudaGetSymbolAddress(&p_awlo, g_awlo);
    cudaGetSymbolAddress(&p_m1hi, g_m1hi); cudaGetSymbolAddress(&p_m1lo, g_m1lo);

    cudaFuncSetAttribute(mma_gemm_k<256, 0, true>,
                         cudaFuncAttributeMaxDynamicSharedMemorySize, GEMM_SMEM);
    cudaFuncSetAttribute(mma_gemm_k<512, 1, false>,
                         cudaFuncAttributeMaxDynamicSharedMemorySize, GEMM_SMEM);
    cudaFuncSetAttribute(mma_gemm_k<256, 2, false>,
                         cudaFuncAttributeMaxDynamicSharedMemorySize, GEMM_SMEM);
    cudaFuncSetAttribute(pairs_mma_k,
                         cudaFuncAttributeMaxDynamicSharedMemorySize, PAIRS_SMEM);

    // Side stream + fork/join events for pairs ∥ att concurrency. Host-side
    // handles only; created per call, intentionally not destroyed (destroying
    // capture-referenced handles mid-capture is UB; calls are few).
    cudaStream_t s1;
    cudaEvent_t eFork, eJoin;
    cudaStreamCreateWithFlags(&s1, cudaStreamNonBlocking);
    cudaEventCreateWithFlags(&eFork, cudaEventDisableTiming);
    cudaEventCreateWithFlags(&eJoin, cudaEventDisableTiming);

    // split ALL weights in one launch (emb is split in-register inside fm1)
    splitw_k<<<(WTOT + 255) / 256, 256>>>(
        fm_w1, fm_w2, att_w, mlp_w1,
        (__nv_bfloat16*)p_w1hi, (__nv_bfloat16*)p_w1lo,
        (__nv_bfloat16*)p_w2hi, (__nv_bfloat16*)p_w2lo,
        (__nv_bfloat16*)p_awhi, (__nv_bfloat16*)p_awlo,
        (__nv_bfloat16*)p_m1hi, (__nv_bfloat16*)p_m1lo);

    // fm1: gather fp32 emb + in-register split + silu(x @ fm_w1^T + b1) -> h1
    mma_gemm_k<256, 0, true><<<dim3(4, NROW / 128), 256, GEMM_SMEM>>>(
        emb, nullptr, nullptr,
        (const __nv_bfloat16*)p_w1hi, (const __nv_bfloat16*)p_w1lo,
        fm_b1, (__nv_bfloat16*)p_h1hi, (__nv_bfloat16*)p_h1lo, nullptr, team_ids, 512);
    // fm2: h1 @ fm_w2^T + b2 -> h (hi/lo)
    mma_gemm_k<512, 1, false><<<dim3(2, NROW / 128), 256, GEMM_SMEM>>>(
        nullptr, (const __nv_bfloat16*)p_h1hi, (const __nv_bfloat16*)p_h1lo,
        (const __nv_bfloat16*)p_w2hi, (const __nv_bfloat16*)p_w2lo,
        fm_b2, (__nv_bfloat16*)p_hhi, (__nv_bfloat16*)p_hlo, nullptr, nullptr, 256);

    // fork: pairs on the main stream ∥ att on s1
    cudaEventRecord(eFork, 0);
    cudaStreamWaitEvent(s1, eFork, 0);

    // pairs (main stream, launched first so ncu's capture slot lands on it)
    pairs_mma_k<<<MROW_U / 128, 256, PAIRS_SMEM>>>(
        (const __nv_bfloat16*)p_hhi, (const __nv_bfloat16*)p_hlo,
        (const __nv_bfloat16*)p_m1hi, (const __nv_bfloat16*)p_m1lo,
        mlp_b1, mlp_w2, (float*)p_o2);

    // att (on s1): h @ att_w^T + att_b -> wh (fp32)
    mma_gemm_k<256, 2, false><<<dim3(2, NROW / 128), 256, GEMM_SMEM, s1>>>(
        nullptr, (const __nv_bfloat16*)p_hhi, (const __nv_bfloat16*)p_hlo,
        (const __nv_bfloat16*)p_awhi, (const __nv_bfloat16*)p_awlo,
        att_b, nullptr, nullptr, (float*)p_wh, nullptr, 256);
    cudaEventRecord(eJoin, s1);

    // join: final needs both o2 (main) and wh (s1)
    cudaStreamWaitEvent(0, eJoin, 0);

    // scores + softmax + weighted sum
    final_k<<<BSZ / 4, 128>>>(
        (const __nv_bfloat16*)p_hhi, (const __nv_bfloat16*)p_hlo,
        (const float*)p_wh, (const float*)p_o2, mlp_b2, out);
}

// round 15
// speedup vs baseline: 1.0998x; 1.0998x over previous
#include <cuda_runtime.h>
#include <cuda_bf16.h>
#include <cstdint>

#define TEAMN   5
#define BSZ     16384
#define NROW    (BSZ * TEAMN)     // 81920 member rows
#define NPAIR   20
#define NPAIR_U 10                // unique unordered pairs (prod is symmetric)
#define MROW_U  (BSZ * NPAIR_U)   // 163840 unique pair rows
#define NPLAYER 131072
#define PD      256

// ---------------- scratch (static device globals; no runtime allocation) ----
__device__ __nv_bfloat16 g_h1hi[(size_t)NROW * 512];
__device__ __nv_bfloat16 g_h1lo[(size_t)NROW * 512];
__device__ __nv_bfloat16 g_hhi [(size_t)NROW * 256];
__device__ __nv_bfloat16 g_hlo [(size_t)NROW * 256];
__device__ float         g_wh  [(size_t)NROW * 256];
__device__ float         g_o2  [(size_t)BSZ * NPAIR];
__device__ __nv_bfloat16 g_w1hi[512 * 256], g_w1lo[512 * 256];
__device__ __nv_bfloat16 g_w2hi[256 * 512], g_w2lo[256 * 512];
__device__ __nv_bfloat16 g_awhi[256 * 256], g_awlo[256 * 256];
__device__ __nv_bfloat16 g_m1hi[512 * 256], g_m1lo[512 * 256];

__constant__ int c_i1[NPAIR] = {0,0,0,0, 1,1,1,1, 2,2,2,2, 3,3,3,3, 4,4,4,4};
__constant__ int c_i2[NPAIR] = {1,2,3,4, 0,2,3,4, 0,1,3,4, 0,1,2,4, 0,1,2,3};
__constant__ int c_u1[NPAIR_U] = {0,0,0,0, 1,1,1, 2,2, 3};
__constant__ int c_u2[NPAIR_U] = {1,2,3,4, 2,3,4, 3,4, 4};
__constant__ int c_sA[NPAIR_U] = {0,1,2,3, 5,6,7, 10,11, 15};
__constant__ int c_sB[NPAIR_U] = {4,8,12,16, 9,13,17, 14,18, 19};

__device__ __forceinline__ float siluf(float x) { return x / (1.0f + __expf(-x)); }

__device__ __forceinline__ unsigned smem_u32(const void* p) {
    return (unsigned)__cvta_generic_to_shared(p);
}
__device__ __forceinline__ void ldsm_x4(uint32_t* r, unsigned addr) {
    asm volatile("ldmatrix.sync.aligned.m8n8.x4.shared.b16 {%0,%1,%2,%3}, [%4];"
                 : "=r"(r[0]), "=r"(r[1]), "=r"(r[2]), "=r"(r[3]) : "r"(addr));
}
// one x4 delivering B fragments for TWO adjacent n-tiles (k16 each)
__device__ __forceinline__ void ldsm_x4_b2(uint32_t* b0, uint32_t* b1, unsigned addr) {
    asm volatile("ldmatrix.sync.aligned.m8n8.x4.shared.b16 {%0,%1,%2,%3}, [%4];"
                 : "=r"(b0[0]), "=r"(b0[1]), "=r"(b1[0]), "=r"(b1[1]) : "r"(addr));
}
__device__ __forceinline__ void mma16816(float* c, const uint32_t* a, const uint32_t* b) {
    asm volatile(
        "mma.sync.aligned.m16n8k16.row.col.f32.bf16.bf16.f32 "
        "{%0,%1,%2,%3}, {%4,%5,%6,%7}, {%8,%9}, {%0,%1,%2,%3};"
        : "+f"(c[0]), "+f"(c[1]), "+f"(c[2]), "+f"(c[3])
        : "r"(a[0]), "r"(a[1]), "r"(a[2]), "r"(a[3]), "r"(b[0]), "r"(b[1]));
}
__device__ __forceinline__ void cp16(unsigned saddr, const void* g) {
    asm volatile("cp.async.cg.shared.global [%0], [%1], 16;" :: "r"(saddr), "l"(g));
}
#define CP_COMMIT() asm volatile("cp.async.commit_group;" ::: "memory")
#define CP_WAIT1()  asm volatile("cp.async.wait_group 1;" ::: "memory")
#define CP_WAIT0()  asm volatile("cp.async.wait_group 0;" ::: "memory")

__device__ __forceinline__ void store_split2(__nv_bfloat16* hi, __nv_bfloat16* lo,
                                             size_t off, float y0, float y1) {
    __nv_bfloat16 h0 = __float2bfloat16(y0), h1 = __float2bfloat16(y1);
    *(__nv_bfloat162*)(hi + off) = __halves2bfloat162(h0, h1);
    *(__nv_bfloat162*)(lo + off) = __halves2bfloat162(
        __float2bfloat16(y0 - __bfloat162float(h0)),
        __float2bfloat16(y1 - __bfloat162float(h1)));
}

// ---------------------------------------------------------------------------
// Combined weight split: fm_w1, fm_w2, att_w, mlp_w1 -> (hi, lo) bf16 pairs
// ---------------------------------------------------------------------------
#define W1_N 131072
#define W2_N 131072
#define AW_N 65536
#define M1_N 131072
#define WTOT (W1_N + W2_N + AW_N + M1_N)

__global__ void splitw_k(const float* __restrict__ w1, const float* __restrict__ w2,
                         const float* __restrict__ aw, const float* __restrict__ m1,
                         __nv_bfloat16* __restrict__ w1h, __nv_bfloat16* __restrict__ w1l,
                         __nv_bfloat16* __restrict__ w2h, __nv_bfloat16* __restrict__ w2l,
                         __nv_bfloat16* __restrict__ awh, __nv_bfloat16* __restrict__ awl,
                         __nv_bfloat16* __restrict__ m1h, __nv_bfloat16* __restrict__ m1l)
{
    int i = blockIdx.x * 256 + threadIdx.x;
    if (i >= WTOT) return;
    const float* s; __nv_bfloat16 *hi, *lo; int j = i;
    if (j < W1_N)                { s = w1; hi = w1h; lo = w1l; }
    else if ((j -= W1_N) < W2_N) { s = w2; hi = w2h; lo = w2l; }
    else if ((j -= W2_N) < AW_N) { s = aw; hi = awh; lo = awl; }
    else { j -= AW_N;              s = m1; hi = m1h; lo = m1l; }
    float v = s[j];
    __nv_bfloat16 h = __float2bfloat16(v);
    hi[j] = h;
    lo[j] = __float2bfloat16(v - __bfloat162float(h));
}

// ---------------------------------------------------------------------------
// MERGED split-bf16 GEMM, 3-stage cp.async pipeline, ONE sync per K-chunk.
// (R11 kernel, proven — unchanged.)
// ---------------------------------------------------------------------------
#define GEMM_SMEM  98304          // 3 x 32768
#define STAGE_B    32768
#define TILE_B     8192           // 128 x 64 bytes

template <int K, int EP, bool GATHER>
__global__ __launch_bounds__(256, 2)
void mma_gemm_k(const float* __restrict__ Af,
                const __nv_bfloat16* __restrict__ Ahi, const __nv_bfloat16* __restrict__ Alo,
                const __nv_bfloat16* __restrict__ Whi, const __nv_bfloat16* __restrict__ Wlo,
                const float* __restrict__ bias,
                __nv_bfloat16* __restrict__ Chi, __nv_bfloat16* __restrict__ Clo,
                float* __restrict__ Cf, const int* __restrict__ ids, int N)
{
    constexpr int NC = K / 32;
    extern __shared__ __align__(16) __nv_bfloat16 smdyn[];
    __shared__ int idS[128];

    const int t = threadIdx.x;
    const int lane = t & 31, warp = t >> 5;
    const int wm = warp >> 2, wn = warp & 3;
    const int m0 = blockIdx.y * 128, n0 = blockIdx.x * 128;

    if constexpr (GATHER) {
        if (t < 128) idS[t] = ids[m0 + t];
        __syncthreads();
    }

    const int r0 = t >> 2, cc = t & 3;
    const int r1 = r0 + 64;
    const unsigned d0 = (unsigned)(r0 * 64 + ((cc ^ ((r0 >> 1) & 3)) << 4));
    const unsigned d1 = (unsigned)(r1 * 64 + ((cc ^ ((r1 >> 1) & 3)) << 4));
    const int srcoff = cc * 8;
    const unsigned smB = smem_u32(smdyn);

    float acc[4][4][4];
#pragma unroll
    for (int a = 0; a < 4; a++)
#pragma unroll
        for (int b = 0; b < 4; b++)
#pragma unroll
            for (int c = 0; c < 4; c++) acc[a][b][c] = 0.f;

    const int a_mrow = ((lane >> 3) & 1) * 8 + (lane & 7);
    const int a_c16  = lane >> 4;
    const int b_nrow = ((lane >> 4) & 1) * 8 + (lane & 7);
    const int b_c16  = (lane >> 3) & 1;

    auto issue = [&](int c) {
        const int koff = c * 32 + srcoff;
        const unsigned sb = smB + (unsigned)((c % 3) * STAGE_B);
        if constexpr (!GATHER) {
            cp16(sb + d0,              Ahi + (size_t)(m0 + r0) * K + koff);
            cp16(sb + d1,              Ahi + (size_t)(m0 + r1) * K + koff);
            cp16(sb + TILE_B + d0,     Alo + (size_t)(m0 + r0) * K + koff);
            cp16(sb + TILE_B + d1,     Alo + (size_t)(m0 + r1) * K + koff);
        }
        cp16(sb + 2 * TILE_B + d0,     Whi + (size_t)(n0 + r0) * K + koff);
        cp16(sb + 2 * TILE_B + d1,     Whi + (size_t)(n0 + r1) * K + koff);
        cp16(sb + 3 * TILE_B + d0,     Wlo + (size_t)(n0 + r0) * K + koff);
        cp16(sb + 3 * TILE_B + d1,     Wlo + (size_t)(n0 + r1) * K + koff);
        CP_COMMIT();
    };

    float4 rf[4];
    auto ldgA = [&](int c) {
        const int koff = c * 32 + srcoff;
        const float* s0 = Af + (size_t)idS[r0] * K + koff;
        rf[0] = *(const float4*)s0; rf[1] = *(const float4*)(s0 + 4);
        const float* s1 = Af + (size_t)idS[r1] * K + koff;
        rf[2] = *(const float4*)s1; rf[3] = *(const float4*)(s1 + 4);
    };
    auto stsA = [&](int c) {
        char* base = (char*)smdyn + (c % 3) * STAGE_B;
#pragma unroll
        for (int u = 0; u < 2; u++) {
            const float* f = (const float*)&rf[2 * u];
            const unsigned dd = (u == 0) ? d0 : d1;
            __nv_bfloat16 vh[8], vl[8];
#pragma unroll
            for (int j = 0; j < 8; j++) {
                __nv_bfloat16 h = __float2bfloat16(f[j]);
                vh[j] = h;
                vl[j] = __float2bfloat16(f[j] - __bfloat162float(h));
            }
            *(uint4*)(base + dd)          = *(uint4*)vh;
            *(uint4*)(base + TILE_B + dd) = *(uint4*)vl;
        }
    };

    issue(0);
    issue(1);
    if constexpr (GATHER) ldgA(0);

    for (int c = 0; c < NC; c++) {
        if (c + 1 < NC) { CP_WAIT1(); } else { CP_WAIT0(); }
        if constexpr (GATHER) stsA(c);
        __syncthreads();
        if (c + 2 < NC) issue(c + 2);
        if constexpr (GATHER) { if (c + 1 < NC) ldgA(c + 1); }

        const unsigned sb  = smB + (unsigned)((c % 3) * STAGE_B);
        const unsigned aHi = sb;
        const unsigned aLo = sb + TILE_B;
        const unsigned wHi = sb + 2 * TILE_B;
        const unsigned wLo = sb + 3 * TILE_B;
#pragma unroll
        for (int ks = 0; ks < 2; ks++) {
            uint32_t bh[4][2], bl[4][2];
#pragma unroll
            for (int ntp = 0; ntp < 2; ntp++) {
                const int br = wn * 32 + ntp * 16 + b_nrow;
                const int bc = ks * 2 + b_c16;
                const unsigned wo = (unsigned)(br * 64 + ((bc ^ ((br >> 1) & 3)) << 4));
                ldsm_x4_b2(bh[2 * ntp], bh[2 * ntp + 1], wHi + wo);
                ldsm_x4_b2(bl[2 * ntp], bl[2 * ntp + 1], wLo + wo);
            }
#pragma unroll
            for (int mt = 0; mt < 4; mt++) {
                const int ar = wm * 64 + mt * 16 + a_mrow;
                const int ac = ks * 2 + a_c16;
                const unsigned ao = (unsigned)(ar * 64 + ((ac ^ ((ar >> 1) & 3)) << 4));
                uint32_t afh[4], afl[4];
                ldsm_x4(afh, aHi + ao);
                ldsm_x4(afl, aLo + ao);
#pragma unroll
                for (int nt = 0; nt < 4; nt++) mma16816(acc[mt][nt], afh, bh[nt]);
#pragma unroll
                for (int nt = 0; nt < 4; nt++) mma16816(acc[mt][nt], afl, bh[nt]);
#pragma unroll
                for (int nt = 0; nt < 4; nt++) mma16816(acc[mt][nt], afh, bl[nt]);
            }
        }
    }

#pragma unroll
    for (int mt = 0; mt < 4; mt++)
#pragma unroll
        for (int nt = 0; nt < 4; nt++) {
            int row = m0 + wm * 64 + mt * 16 + (lane >> 2);
            int col = n0 + wn * 32 + nt * 8 + ((lane & 3) << 1);
            float2 bz = *(const float2*)(bias + col);
            float* c = acc[mt][nt];
            float y0 = c[0] + bz.x, y1 = c[1] + bz.y;
            float y2 = c[2] + bz.x, y3 = c[3] + bz.y;
            if (EP == 0) { y0 = siluf(y0); y1 = siluf(y1); y2 = siluf(y2); y3 = siluf(y3); }
            if (EP <= 1) {
                store_split2(Chi, Clo, (size_t)row * N + col, y0, y1);
                store_split2(Chi, Clo, (size_t)(row + 8) * N + col, y2, y3);
            } else {
                *(float2*)(Cf + (size_t)row * N + col)       = make_float2(y0, y1);
                *(float2*)(Cf + (size_t)(row + 8) * N + col) = make_float2(y2, y3);
            }
        }
}

// ---------------------------------------------------------------------------
// Pair-MLP over UNIQUE pairs — 512 threads / 16 warps (4x4 warp grid).
// Same smem layout, W stream, and per-element MMA order as R14 (bit-identical
// output); each warp now owns 32x32 of the 128x128 n-chunk (acc[2][4][4]),
// doubling warps/SMSP from 2 to 4 to feed the HMMA pipe.
// ---------------------------------------------------------------------------
#define PR_APLO   67584
#define PR_W      135168
#define PR_WST    20480          // per stage: hi 10240 + lo 10240
#define PR_OFF1   196608
#define PR_OFF2   197120
#define PR_RED    197632
#define PAIRS_SMEM 199680

__global__ __launch_bounds__(512, 1)
void pairs_mma_k(const __nv_bfloat16* __restrict__ Hhi, const __nv_bfloat16* __restrict__ Hlo,
                 const __nv_bfloat16* __restrict__ W1hi, const __nv_bfloat16* __restrict__ W1lo,
                 const float* __restrict__ b1, const float* __restrict__ w2,
                 float* __restrict__ O2)
{
    extern __shared__ __align__(16) char sm[];
    __nv_bfloat16* Aphi = (__nv_bfloat16*)sm;               // [128][264]
    __nv_bfloat16* Aplo = (__nv_bfloat16*)(sm + PR_APLO);   // [128][264]
    int*   off1s = (int*)(sm + PR_OFF1);
    int*   off2s = (int*)(sm + PR_OFF2);
    float* redS  = (float*)(sm + PR_RED);                   // [4][128]

    const int t = threadIdx.x, lane = t & 31, warp = t >> 5; // warp 0..15
    const int wm = warp >> 2, wn = warp & 3;                 // 4x4 grid
    const int m0 = blockIdx.x * 128;
    const unsigned smB = smem_u32(sm);

    if (t < 128) {
        int r = m0 + t, b = r / NPAIR_U, p = r - b * NPAIR_U;
        off1s[t] = (b * TEAMN + c_u1[p]) * 256;
        off2s[t] = (b * TEAMN + c_u2[p]) * 256;
    }
    __syncthreads();

    // W stream: 32 chunks (nn 0..3, kk 0..7), 3-stage cp.async; 512 threads
    // cover the full 128x32 hi+lo chunk in one pass.
    auto issueW = [&](int gg) {
        const int nn = gg >> 3, kk = gg & 7;
        const unsigned sb = smB + (unsigned)(PR_W + (gg % 3) * PR_WST);
        const int row = t >> 2, c16 = t & 3;
        const unsigned dst = (unsigned)(row * 80 + c16 * 16);
        const size_t src = (size_t)(nn * 128 + row) * 256 + kk * 32 + c16 * 8;
        cp16(sb + dst,         W1hi + src);
        cp16(sb + 10240 + dst, W1lo + src);
        CP_COMMIT();
    };

    // prologue W loads overlap the product-build phase below
    issueW(0);
    issueW(1);

    // ---- build product tiles (hi/lo) — layout unchanged; 8 iters @512thr ----
    {
        int cidx = t;
#pragma unroll 4
        for (int i = 0; i < 8; i++, cidx += 512) {
            int row = cidx >> 5;
            int ch  = (cidx & 31) << 3;
            int o1 = off1s[row] + ch, o2 = off2s[row] + ch;
            uint4 u1h = *(const uint4*)(Hhi + o1);
            uint4 u1l = *(const uint4*)(Hlo + o1);
            uint4 u2h = *(const uint4*)(Hhi + o2);
            uint4 u2l = *(const uint4*)(Hlo + o2);
            const __nv_bfloat162* p1h = (const __nv_bfloat162*)&u1h;
            const __nv_bfloat162* p1l = (const __nv_bfloat162*)&u1l;
            const __nv_bfloat162* p2h = (const __nv_bfloat162*)&u2h;
            const __nv_bfloat162* p2l = (const __nv_bfloat162*)&u2l;
            __nv_bfloat162 oph[4], opl[4];
#pragma unroll
            for (int j = 0; j < 4; j++) {
                float2 a   = __bfloat1622float2(p1h[j]);
                float2 al  = __bfloat1622float2(p1l[j]);
                float2 b_  = __bfloat1622float2(p2h[j]);
                float2 bl_ = __bfloat1622float2(p2l[j]);
                float f0 = (a.x + al.x) * (b_.x + bl_.x);
                float f1 = (a.y + al.y) * (b_.y + bl_.y);
                __nv_bfloat16 h0 = __float2bfloat16(f0), h1 = __float2bfloat16(f1);
                oph[j] = __halves2bfloat162(h0, h1);
                opl[j] = __halves2bfloat162(
                    __float2bfloat16(f0 - __bfloat162float(h0)),
                    __float2bfloat16(f1 - __bfloat162float(h1)));
            }
            *(uint4*)(Aphi + row * 264 + ch) = *(uint4*)oph;
            *(uint4*)(Aplo + row * 264 + ch) = *(uint4*)opl;
        }
    }

    float rowsum[2][2];
#pragma unroll
    for (int a = 0; a < 2; a++) { rowsum[a][0] = 0.f; rowsum[a][1] = 0.f; }

    const int a_mrow = ((lane >> 3) & 1) * 8 + (lane & 7);
    const int a_kc   = (lane >> 4) * 8;
    const int b_nrow = ((lane >> 4) & 1) * 8 + (lane & 7);
    const int b_kc   = ((lane >> 3) & 1) * 8;
    const unsigned aPhiB = smem_u32(Aphi);
    const unsigned aPloB = smem_u32(Aplo);

    for (int n0i = 0; n0i < 4; n0i++) {
        int n0 = n0i * 128;
        float acc[2][4][4];
#pragma unroll
        for (int a = 0; a < 2; a++)
#pragma unroll
            for (int b = 0; b < 4; b++)
#pragma unroll
                for (int c = 0; c < 4; c++) acc[a][b][c] = 0.f;

        for (int k0 = 0; k0 < 8; k0++) {
            const int gg = n0i * 8 + k0;
            if (gg + 1 < 32) { CP_WAIT1(); } else { CP_WAIT0(); }
            __syncthreads();
            if (gg + 2 < 32) issueW(gg + 2);

            const unsigned wHiB = smB + (unsigned)(PR_W + (gg % 3) * PR_WST);
            const unsigned wLoB = wHiB + 10240;
#pragma unroll
            for (int ks = 0; ks < 2; ks++) {
                int kpos = k0 * 32 + ks * 16;
                uint32_t bh[4][2], blo_[4][2];
#pragma unroll
                for (int ntp = 0; ntp < 2; ntp++) {
                    unsigned wo = 2u * ((wn * 32 + ntp * 16 + b_nrow) * 40 + ks * 16 + b_kc);
                    ldsm_x4_b2(bh[2 * ntp],   bh[2 * ntp + 1],   wHiB + wo);
                    ldsm_x4_b2(blo_[2 * ntp], blo_[2 * ntp + 1], wLoB + wo);
                }
#pragma unroll
                for (int mt = 0; mt < 2; mt++) {
                    unsigned ao = (wm * 32 + mt * 16 + a_mrow) * 264 + kpos + a_kc;
                    uint32_t af[4];
                    ldsm_x4(af, aPhiB + 2u * ao);
#pragma unroll
                    for (int nt = 0; nt < 4; nt++) mma16816(acc[mt][nt], af, bh[nt]);
#pragma unroll
                    for (int nt = 0; nt < 4; nt++) mma16816(acc[mt][nt], af, blo_[nt]);
                    ldsm_x4(af, aPloB + 2u * ao);
#pragma unroll
                    for (int nt = 0; nt < 4; nt++) mma16816(acc[mt][nt], af, bh[nt]);
                }
            }
        }
        // fold this n-chunk into rowsums
#pragma unroll
        for (int mt = 0; mt < 2; mt++)
#pragma unroll
            for (int nt = 0; nt < 4; nt++) {
                int col = n0 + wn * 32 + nt * 8 + ((lane & 3) << 1);
                float2 bz = *(const float2*)(b1 + col);
                float2 wz = *(const float2*)(w2 + col);
                float* c = acc[mt][nt];
                rowsum[mt][0] += siluf(c[0] + bz.x) * wz.x + siluf(c[1] + bz.y) * wz.y;
                rowsum[mt][1] += siluf(c[2] + bz.x) * wz.x + siluf(c[3] + bz.y) * wz.y;
            }
    }

    // reduce over the 4 lanes sharing a row, then across the 4 n-warps
#pragma unroll
    for (int mt = 0; mt < 2; mt++)
#pragma unroll
        for (int p = 0; p < 2; p++) {
            float v = rowsum[mt][p];
            v += __shfl_xor_sync(0xffffffffu, v, 1);
            v += __shfl_xor_sync(0xffffffffu, v, 2);
            rowsum[mt][p] = v;
        }
    __syncthreads();
    if ((lane & 3) == 0) {
#pragma unroll
        for (int mt = 0; mt < 2; mt++)
#pragma unroll
            for (int p = 0; p < 2; p++) {
                int r = wm * 32 + mt * 16 + (lane >> 2) + p * 8;
                redS[wn * 128 + r] = rowsum[mt][p];
            }
    }
    __syncthreads();
    if (t < 128) {
        float v = redS[t] + redS[128 + t] + redS[256 + t] + redS[384 + t];
        int r = m0 + t, b = r / NPAIR_U, p = r - b * NPAIR_U;
        O2[b * NPAIR + c_sA[p]] = v;   // (i,j)
        O2[b * NPAIR + c_sB[p]] = v;   // (j,i) — identical by symmetry
    }
}

// ---------------------------------------------------------------------------
// Final: score[p] = <wh[b,i1], h[b,i2]>, softmax per group-of-4, weighted sum.
// ---------------------------------------------------------------------------
__global__ __launch_bounds__(128)
void final_k(const __nv_bfloat16* __restrict__ Hhi, const __nv_bfloat16* __restrict__ Hlo,
             const float* __restrict__ WH, const float* __restrict__ O2,
             const float* __restrict__ mlp_b2, float* __restrict__ out)
{
    __shared__ float scoreS[4][NPAIR];
    const int wi = threadIdx.x >> 5, lane = threadIdx.x & 31;
    const int b = blockIdx.x * 4 + wi;
    const __nv_bfloat16* hbh = Hhi + (size_t)b * TEAMN * 256;
    const __nv_bfloat16* hbl = Hlo + (size_t)b * TEAMN * 256;
    const float* whb = WH + (size_t)b * TEAMN * 256;

    for (int p = 0; p < NPAIR; p++) {
        const float* wa = whb + c_i1[p] * 256;
        int ho = c_i2[p] * 256 + lane * 8;
        uint4 uh = *(const uint4*)(hbh + ho);
        uint4 ul = *(const uint4*)(hbl + ho);
        const __nv_bfloat162* ph = (const __nv_bfloat162*)&uh;
        const __nv_bfloat162* pl = (const __nv_bfloat162*)&ul;
        float xv[8];
        *(float4*)&xv[0] = *(const float4*)(wa + lane * 8);
        *(float4*)&xv[4] = *(const float4*)(wa + lane * 8 + 4);
        float s = 0.f;
#pragma unroll
        for (int j = 0; j < 4; j++) {
            float2 hh = __bfloat1622float2(ph[j]);
            float2 hl = __bfloat1622float2(pl[j]);
            s += xv[2 * j] * (hh.x + hl.x) + xv[2 * j + 1] * (hh.y + hl.y);
        }
#pragma unroll
        for (int off = 16; off > 0; off >>= 1)
            s += __shfl_down_sync(0xffffffffu, s, off);
        if (lane == 0) scoreS[wi][p] = s;
    }
    __syncwarp();

    float partial = 0.f;
    if (lane < TEAMN) {
        float sc[4];
#pragma unroll
        for (int j = 0; j < 4; j++) sc[j] = scoreS[wi][lane * 4 + j];
        float mx = fmaxf(fmaxf(sc[0], sc[1]), fmaxf(sc[2], sc[3]));
        float e[4], se = 0.f;
#pragma unroll
        for (int j = 0; j < 4; j++) { e[j] = __expf(sc[j] - mx); se += e[j]; }
        float bias2 = mlp_b2[0];
        float acc = 0.f;
#pragma unroll
        for (int j = 0; j < 4; j++)
            acc += e[j] * (O2[b * NPAIR + lane * 4 + j] + bias2);
        partial = acc / se;
    }
#pragma unroll
    for (int off = 16; off > 0; off >>= 1)
        partial += __shfl_down_sync(0xffffffffu, partial, off);
    if (lane == 0) out[b] = partial;
}

// ---------------------------------------------------------------------------
extern "C" void kernel_launch(void* const* d_in, const int* in_sizes, int n_in,
                              void* d_out, int out_size)
{
    const int*   team_ids = (const int*)  d_in[0];
    const float* emb      = (const float*)d_in[1];
    const float* fm_w1    = (const float*)d_in[2];
    const float* fm_b1    = (const float*)d_in[3];
    const float* fm_w2    = (const float*)d_in[4];
    const float* fm_b2    = (const float*)d_in[5];
    const float* att_w    = (const float*)d_in[6];
    const float* att_b    = (const float*)d_in[7];
    const float* mlp_w1   = (const float*)d_in[8];
    const float* mlp_b1   = (const float*)d_in[9];
    const float* mlp_w2   = (const float*)d_in[10];
    const float* mlp_b2   = (const float*)d_in[11];
    float* out = (float*)d_out;

    void *p_h1hi, *p_h1lo, *p_hhi, *p_hlo, *p_wh, *p_o2;
    void *p_w1hi, *p_w1lo, *p_w2hi, *p_w2lo, *p_awhi, *p_awlo, *p_m1hi, *p_m1lo;
    cudaGetSymbolAddress(&p_h1hi, g_h1hi); cudaGetSymbolAddress(&p_h1lo, g_h1lo);
    cudaGetSymbolAddress(&p_hhi,  g_hhi);  cudaGetSymbolAddress(&p_hlo,  g_hlo);
    cudaGetSymbolAddress(&p_wh,   g_wh);   cudaGetSymbolAddress(&p_o2,   g_o2);
    cudaGetSymbolAddress(&p_w1hi, g_w1hi); cudaGetSymbolAddress(&p_w1lo, g_w1lo);
    cudaGetSymbolAddress(&p_w2hi, g_w2hi); cudaGetSymbolAddress(&p_w2lo, g_w2lo);
    cudaGetSymbolAddress(&p_awhi, g_awhi); cudaGetSymbolAddress(&p_awlo, g_awlo);
    cudaGetSymbolAddress(&p_m1hi, g_m1hi); cudaGetSymbolAddress(&p_m1lo, g_m1lo);

    cudaFuncSetAttribute(mma_gemm_k<256, 0, true>,
                         cudaFuncAttributeMaxDynamicSharedMemorySize, GEMM_SMEM);
    cudaFuncSetAttribute(mma_gemm_k<512, 1, false>,
                         cudaFuncAttributeMaxDynamicSharedMemorySize, GEMM_SMEM);
    cudaFuncSetAttribute(mma_gemm_k<256, 2, false>,
                         cudaFuncAttributeMaxDynamicSharedMemorySize, GEMM_SMEM);
    cudaFuncSetAttribute(pairs_mma_k,
                         cudaFuncAttributeMaxDynamicSharedMemorySize, PAIRS_SMEM);

    // Side stream + fork/join events for pairs ∥ att concurrency. Host-side
    // handles only; created per call, intentionally not destroyed (destroying
    // capture-referenced handles mid-capture is UB; calls are few).
    cudaStream_t s1;
    cudaEvent_t eFork, eJoin;
    cudaStreamCreateWithFlags(&s1, cudaStreamNonBlocking);
    cudaEventCreateWithFlags(&eFork, cudaEventDisableTiming);
    cudaEventCreateWithFlags(&eJoin, cudaEventDisableTiming);

    // split ALL weights in one launch (emb is split in-register inside fm1)
    splitw_k<<<(WTOT + 255) / 256, 256>>>(
        fm_w1, fm_w2, att_w, mlp_w1,
        (__nv_bfloat16*)p_w1hi, (__nv_bfloat16*)p_w1lo,
        (__nv_bfloat16*)p_w2hi, (__nv_bfloat16*)p_w2lo,
        (__nv_bfloat16*)p_awhi, (__nv_bfloat16*)p_awlo,
        (__nv_bfloat16*)p_m1hi, (__nv_bfloat16*)p_m1lo);

    // fm1: gather fp32 emb + in-register split + silu(x @ fm_w1^T + b1) -> h1
    mma_gemm_k<256, 0, true><<<dim3(4, NROW / 128), 256, GEMM_SMEM>>>(
        emb, nullptr, nullptr,
        (const __nv_bfloat16*)p_w1hi, (const __nv_bfloat16*)p_w1lo,
        fm_b1, (__nv_bfloat16*)p_h1hi, (__nv_bfloat16*)p_h1lo, nullptr, team_ids, 512);
    // fm2: h1 @ fm_w2^T + b2 -> h (hi/lo)
    mma_gemm_k<512, 1, false><<<dim3(2, NROW / 128), 256, GEMM_SMEM>>>(
        nullptr, (const __nv_bfloat16*)p_h1hi, (const __nv_bfloat16*)p_h1lo,
        (const __nv_bfloat16*)p_w2hi, (const __nv_bfloat16*)p_w2lo,
        fm_b2, (__nv_bfloat16*)p_hhi, (__nv_bfloat16*)p_hlo, nullptr, nullptr, 256);

    // fork: pairs on the main stream ∥ att on s1
    cudaEventRecord(eFork, 0);
    cudaStreamWaitEvent(s1, eFork, 0);

    // pairs (main stream; 512 threads)
    pairs_mma_k<<<MROW_U / 128, 512, PAIRS_SMEM>>>(
        (const __nv_bfloat16*)p_hhi, (const __nv_bfloat16*)p_hlo,
        (const __nv_bfloat16*)p_m1hi, (const __nv_bfloat16*)p_m1lo,
        mlp_b1, mlp_w2, (float*)p_o2);

    // att (on s1): h @ att_w^T + att_b -> wh (fp32)
    mma_gemm_k<256, 2, false><<<dim3(2, NROW / 128), 256, GEMM_SMEM, s1>>>(
        nullptr, (const __nv_bfloat16*)p_hhi, (const __nv_bfloat16*)p_hlo,
        (const __nv_bfloat16*)p_awhi, (const __nv_bfloat16*)p_awlo,
        att_b, nullptr, nullptr, (float*)p_wh, nullptr, 256);
    cudaEventRecord(eJoin, s1);

    // join: final needs both o2 (main) and wh (s1)
    cudaStreamWaitEvent(0, eJoin, 0);

    // scores + softmax + weighted sum
    final_k<<<BSZ / 4, 128>>>(
        (const __nv_bfloat16*)p_hhi, (const __nv_bfloat16*)p_hlo,
        (const float*)p_wh, (const float*)p_o2, mlp_b2, out);
}